// round 5
// baseline (speedup 1.0000x reference)
#include <cuda_runtime.h>
#include <cuda_fp16.h>
#include <cstdint>
#include <cstddef>

#define NE    160000
#define NN    10000
#define HID   300
#define PAD   320
#define LDIM  32
#define MRWS  160000

// ---------------- scratch (static __device__, allocation-free) ----------------
__device__ float  g_bufA[(size_t)MRWS * PAD];   // 204.8 MB
__device__ float  g_bufB[(size_t)MRWS * PAD];   // 204.8 MB
__device__ float  g_hwS[(size_t)NN * PAD];      // 12.8 MB raw hw, rows < NN
__device__ __half g_BT[(size_t)5 * 2 * PAD * PAD];  // weights: [layer][hi/lo][n][k]
__device__ int    g_cnt[NN];
__device__ float  g_dinv[NN];
__device__ int    g_rowptr[NN + 1];
__device__ int    g_fill[NN];
__device__ int    g_eid[NE];
__device__ int    g_src[NE];
__device__ float  g_val[NE];
__device__ float  g_part[625 * PAD];

#define MMA_F16(c, a, b)                                                      \
    asm volatile("mma.sync.aligned.m16n8k16.row.col.f32.f16.f16.f32 "         \
        "{%0,%1,%2,%3}, {%4,%5,%6,%7}, {%8,%9}, {%0,%1,%2,%3};"               \
        : "+f"((c)[0]), "+f"((c)[1]), "+f"((c)[2]), "+f"((c)[3])              \
        : "r"((a)[0]), "r"((a)[1]), "r"((a)[2]), "r"((a)[3]),                 \
          "r"((b)[0]), "r"((b)[1]))

// ---------------- prep kernels ----------------
__global__ void k_init() {
    int i = blockIdx.x * blockDim.x + threadIdx.x;
    if (i < NN) { g_cnt[i] = 0; g_fill[i] = 0; }
}
__global__ void k_count(const int* __restrict__ ei) {
    int e = blockIdx.x * blockDim.x + threadIdx.x;
    if (e < NE) atomicAdd(&g_cnt[ei[NE + e]], 1);
}
__global__ void k_dinv() {
    int i = blockIdx.x * blockDim.x + threadIdx.x;
    if (i < NN) g_dinv[i] = rsqrtf((float)(g_cnt[i] + 1));
}
__global__ void k_scan() {
    __shared__ int sm[1024];
    int t = threadIdx.x;
    int v[10]; int loc = 0;
#pragma unroll
    for (int u = 0; u < 10; u++) {
        int idx = t * 10 + u;
        v[u] = (idx < NN) ? g_cnt[idx] : 0;
        loc += v[u];
    }
    sm[t] = loc; __syncthreads();
    for (int off = 1; off < 1024; off <<= 1) {
        int add = (t >= off) ? sm[t - off] : 0;
        __syncthreads();
        sm[t] += add;
        __syncthreads();
    }
    int run = sm[t] - loc;
#pragma unroll
    for (int u = 0; u < 10; u++) {
        int idx = t * 10 + u;
        if (idx < NN) { g_rowptr[idx] = run; run += v[u]; }
    }
    if (t == 0) g_rowptr[NN] = NE;
}
__global__ void k_fillidx(const int* __restrict__ ei) {
    int e = blockIdx.x * blockDim.x + threadIdx.x;
    if (e >= NE) return;
    int c = ei[NE + e];
    int p = atomicAdd(&g_fill[c], 1);
    g_eid[g_rowptr[c] + p] = e;
}
// deterministic per-node ordering: sort edge ids ascending
__global__ void k_sortnode(const int* __restrict__ ei) {
    int i = blockIdx.x * blockDim.x + threadIdx.x;
    if (i >= NN) return;
    int s = g_rowptr[i], d = g_rowptr[i + 1] - s;
    if (d <= 128) {
        int ids[128];
        for (int q = 0; q < d; q++) ids[q] = g_eid[s + q];
        for (int q = 1; q < d; q++) {
            int key = ids[q], p = q - 1;
            while (p >= 0 && ids[p] > key) { ids[p + 1] = ids[p]; p--; }
            ids[p + 1] = key;
        }
        for (int q = 0; q < d; q++) g_eid[s + q] = ids[q];
    } else {
        for (int q = 1; q < d; q++) {
            int key = g_eid[s + q], p = q - 1;
            while (p >= 0 && g_eid[s + p] > key) { g_eid[s + p + 1] = g_eid[s + p]; p--; }
            g_eid[s + p + 1] = key;
        }
    }
    float di = g_dinv[i];
    for (int q = 0; q < d; q++) {
        int e = g_eid[s + q];
        int r = ei[e];
        g_src[s + q] = r;
        g_val[s + q] = g_dinv[r] * di;
    }
}
__global__ void k_edge_embed(const float* __restrict__ attr,
                             const float* __restrict__ w,
                             const float* __restrict__ b) {
    int idx = blockIdx.x * blockDim.x + threadIdx.x;
    if (idx >= NE * LDIM) return;
    int e = idx >> 5, j = idx & 31;
    float a0 = attr[e * 3 + 0], a1 = attr[e * 3 + 1], a2 = attr[e * 3 + 2];
    g_bufA[(size_t)e * PAD + j] = b[j] + a0 * w[j] + a1 * w[32 + j] + a2 * w[64 + j];
}
// Pre-split all layer weights into fp16 hi/lo, transposed [n][k], padded to 320.
__global__ void k_prepB(const float* __restrict__ gcn0_w, const float* __restrict__ gcn_w) {
    int idx = blockIdx.x * blockDim.x + threadIdx.x;   // 5*320*320
    int l   = idx / (PAD * PAD);
    int rem = idx % (PAD * PAD);
    int n   = rem / PAD;
    int k   = rem % PAD;
    int kt  = (l == 0) ? LDIM : HID;
    float w = 0.f;
    if (k < kt && n < HID)
        w = (l == 0) ? gcn0_w[k * HID + n]
                     : gcn_w[(size_t)(l - 1) * HID * HID + k * HID + n];
    __half hi = __float2half_rn(w);
    __half lo = __float2half_rn(w - __half2float(hi));
    size_t base = (size_t)l * 2 * PAD * PAD;
    g_BT[base + (size_t)n * PAD + k]             = hi;
    g_BT[base + (size_t)PAD * PAD + (size_t)n * PAD + k] = lo;
}

// ---------------- fp16 mma.sync GEMM, A-stationary ----------------
// One CTA = 128 rows x ALL 320 cols. A block converted to fp16 ONCE into smem
// (read A from DRAM once per layer), then 5 N-blocks x K-chunks against
// double-buffered B hi/lo tiles (B is L2-resident for all CTAs).
// out = self_norm(m)*C + bias ; raw C -> g_hwS for m < NN.
#define AW_STR   164                        // words per A row (160 + 4 pad)
#define A_WORDS  (128 * AW_STR)             // 20992
#define BW_STR   20
#define B_BUFW   (2 * 64 * BW_STR)          // hi+lo per buffer: 2560 words
#define SMW      (A_WORDS + 2 * B_BUFW)     // 26112 words = 104448 B

template <int RELU>
__global__ __launch_bounds__(256)
void k_gemm(const float* __restrict__ A, const __half* __restrict__ BT,
            const float* __restrict__ bias, float* __restrict__ out, int Kchunks) {
    extern __shared__ uint32_t smu[];
    const int tid  = threadIdx.x;
    const int wid  = tid >> 5, lane = tid & 31;
    const int wm   = wid & 3, wn = wid >> 2;
    const size_t m0 = (size_t)blockIdx.x * 128;
    const int lr = lane >> 2, lc = lane & 3;

    // ---- phase 1: load A block (128 x Kchunks*32) -> fp16 smem, relu fused ----
    {
        const int arow = tid >> 3, ac = (tid & 7) * 4;
        for (int cg = 0; cg < Kchunks * 32; cg += 32) {
#pragma unroll
            for (int p = 0; p < 4; p++) {
                int row = arow + p * 32;
                float4 v = *(const float4*)(A + (m0 + row) * PAD + cg + ac);
                if (RELU) {
                    v.x = fmaxf(v.x, 0.f); v.y = fmaxf(v.y, 0.f);
                    v.z = fmaxf(v.z, 0.f); v.w = fmaxf(v.w, 0.f);
                }
                __half2 h01 = __floats2half2_rn(v.x, v.y);
                __half2 h23 = __floats2half2_rn(v.z, v.w);
                uint2 h;
                h.x = *(uint32_t*)&h01; h.y = *(uint32_t*)&h23;
                *(uint2*)&smu[row * AW_STR + (cg + ac) / 2] = h;
            }
        }
    }
    __syncthreads();

    uint4 pB[2];
    auto ldgB = [&](int n0, int c) {
        int k0 = c * 32;
#pragma unroll
        for (int u = 0; u < 2; u++) {
            int gid = tid + u * 256;                  // 0..511
            int mat = gid >> 8, rem = gid & 255;
            int n = rem >> 2, kw4 = (rem & 3) * 8;    // 8 halves
            pB[u] = *(const uint4*)(BT + (size_t)mat * PAD * PAD +
                                    (size_t)(n0 + n) * PAD + k0 + kw4);
        }
    };
    auto stsB = [&](int buf) {
#pragma unroll
        for (int u = 0; u < 2; u++) {
            int gid = tid + u * 256;
            int mat = gid >> 8, rem = gid & 255;
            int n = rem >> 2, kw4 = (rem & 3) * 4;    // words
            int off = A_WORDS + buf * B_BUFW + mat * 64 * BW_STR + n * BW_STR + kw4;
            *(uint4*)&smu[off] = pB[u];
        }
    };

    // ---- phase 2: loop over 5 N-blocks, K-chunks double-buffered ----
    for (int nb = 0; nb < 5; nb++) {
        const int n0 = nb * 64;
        float acc[2][4][4];
#pragma unroll
        for (int t = 0; t < 2; t++)
#pragma unroll
            for (int j = 0; j < 4; j++)
#pragma unroll
                for (int q = 0; q < 4; q++) acc[t][j][q] = 0.f;

        ldgB(n0, 0);
        stsB(0);
        __syncthreads();
        for (int c = 0; c < Kchunks; c++) {
            if (c + 1 < Kchunks) ldgB(n0, c + 1);
            {
                const int buf = c & 1;
                const uint32_t* Hb = &smu[A_WORDS + buf * B_BUFW];
                const uint32_t* Lb = Hb + 64 * BW_STR;
#pragma unroll
                for (int ks = 0; ks < 2; ks++) {
                    const int aw = c * 16 + ks * 8 + lc;
                    uint32_t af[2][4];
#pragma unroll
                    for (int t = 0; t < 2; t++) {
                        int r = wm * 32 + t * 16 + lr;
                        af[t][0] = smu[r * AW_STR + aw];
                        af[t][1] = smu[(r + 8) * AW_STR + aw];
                        af[t][2] = smu[r * AW_STR + aw + 4];
                        af[t][3] = smu[(r + 8) * AW_STR + aw + 4];
                    }
                    uint32_t bh[4][2], bl[4][2];
#pragma unroll
                    for (int j = 0; j < 4; j++) {
                        int n = wn * 32 + j * 8 + lr;
                        int cw = ks * 8 + lc;
                        bh[j][0] = Hb[n * BW_STR + cw];
                        bh[j][1] = Hb[n * BW_STR + cw + 4];
                        bl[j][0] = Lb[n * BW_STR + cw];
                        bl[j][1] = Lb[n * BW_STR + cw + 4];
                    }
#pragma unroll
                    for (int t = 0; t < 2; t++)
#pragma unroll
                        for (int j = 0; j < 4; j++) {
                            MMA_F16(acc[t][j], af[t], bh[j]);
                            MMA_F16(acc[t][j], af[t], bl[j]);
                        }
                }
            }
            if (c + 1 < Kchunks) {
                stsB((c + 1) & 1);
                __syncthreads();
            }
        }

        // ---- epilogue for this N-block ----
#pragma unroll
        for (int t = 0; t < 2; t++) {
            size_t r0 = m0 + wm * 32 + t * 16 + lr;
            size_t r1 = r0 + 8;
            float sn0 = 1.f, sn1 = 1.f;
            if (r0 < NN) { float dv = g_dinv[r0]; sn0 = dv * dv; }
            if (r1 < NN) { float dv = g_dinv[r1]; sn1 = dv * dv; }
#pragma unroll
            for (int j = 0; j < 4; j++) {
                int col = n0 + wn * 32 + j * 8 + lc * 2;
                float b0 = (col     < HID) ? bias[col]     : 0.f;
                float b1 = (col + 1 < HID) ? bias[col + 1] : 0.f;
                float c0 = acc[t][j][0], c1 = acc[t][j][1];
                float c2 = acc[t][j][2], c3 = acc[t][j][3];
                *(float2*)(out + r0 * PAD + col) = make_float2(fmaf(sn0, c0, b0), fmaf(sn0, c1, b1));
                *(float2*)(out + r1 * PAD + col) = make_float2(fmaf(sn1, c2, b0), fmaf(sn1, c3, b1));
                if (r0 < NN) *(float2*)(g_hwS + r0 * PAD + col) = make_float2(c0, c1);
                if (r1 < NN) *(float2*)(g_hwS + r1 * PAD + col) = make_float2(c2, c3);
            }
        }
        __syncthreads();   // B buffers reused by next N-block
    }
}

// ---------------- CSR gather: out[node] += sum val * hw[src] ----------------
__global__ __launch_bounds__(256)
void k_gather(float* __restrict__ out) {
    int w = (blockIdx.x * 256 + threadIdx.x) >> 5;
    int lane = threadIdx.x & 31;
    if (w >= NN * 10) return;
    int node = w / 10, seg = w % 10;
    int j = seg * 32 + lane;
    int s = g_rowptr[node], e = g_rowptr[node + 1];
    float acc = out[(size_t)node * PAD + j];
    for (int p = s; p < e; p++)
        acc = fmaf(g_val[p], g_hwS[(size_t)g_src[p] * PAD + j], acc);
    out[(size_t)node * PAD + j] = acc;
}

// ---------------- readout ----------------
__global__ void k_mean(const float* __restrict__ h) {
    int j = threadIdx.x;  // 320
    size_t r0 = (size_t)blockIdx.x * 256;
    float acc = 0.f;
    for (int r = 0; r < 256; r++)
        acc += fmaxf(h[(r0 + r) * PAD + j], 0.f);
    g_part[blockIdx.x * PAD + j] = acc;
}
__global__ void k_head(const float* __restrict__ w1, const float* __restrict__ b1,
                       const float* __restrict__ w2, const float* __restrict__ b2,
                       float* __restrict__ out) {
    __shared__ float g[PAD];
    __shared__ float t1[32];
    int t = threadIdx.x;  // 320
    if (t < PAD) {
        float s = 0.f;
        for (int b = 0; b < 625; b++) s += g_part[b * PAD + t];
        g[t] = s * (1.0f / (float)MRWS);
    }
    __syncthreads();
    if (t < 32) {
        float a = b1[t];
        for (int j = 0; j < HID; j++) a = fmaf(g[j], w1[j * 32 + t], a);
        t1[t] = fmaxf(a, 0.f);
    }
    __syncthreads();
    if (t < 2) {
        float a = b2[t];
        for (int k = 0; k < 32; k++) a = fmaf(t1[k], w2[k * 2 + t], a);
        out[t] = a;
    }
}

// ---------------- launch ----------------
extern "C" void kernel_launch(void* const* d_in, const int* in_sizes, int n_in,
                              void* d_out, int out_size) {
    const int*   ei        = (const int*)d_in[1];
    const float* edge_attr = (const float*)d_in[2];
    const float* edge_w    = (const float*)d_in[6];
    const float* edge_b    = (const float*)d_in[7];
    const float* gcn0_w    = (const float*)d_in[8];
    const float* gcn0_b    = (const float*)d_in[9];
    const float* gcn_w     = (const float*)d_in[10];
    const float* gcn_b     = (const float*)d_in[11];
    const float* lin1_w    = (const float*)d_in[12];
    const float* lin1_b    = (const float*)d_in[13];
    const float* lin2_w    = (const float*)d_in[14];
    const float* lin2_b    = (const float*)d_in[15];
    float* out = (float*)d_out;

    cudaFuncSetAttribute(k_gemm<0>, cudaFuncAttributeMaxDynamicSharedMemorySize, SMW * 4);
    cudaFuncSetAttribute(k_gemm<1>, cudaFuncAttributeMaxDynamicSharedMemorySize, SMW * 4);

    float *bufA = nullptr, *bufB = nullptr;
    __half* bt = nullptr;
    cudaGetSymbolAddress((void**)&bufA, g_bufA);
    cudaGetSymbolAddress((void**)&bufB, g_bufB);
    cudaGetSymbolAddress((void**)&bt, g_BT);

    k_init<<<40, 256>>>();
    k_count<<<625, 256>>>(ei);
    k_dinv<<<40, 256>>>();
    k_scan<<<1, 1024>>>();
    k_fillidx<<<625, 256>>>(ei);
    k_sortnode<<<40, 256>>>(ei);
    k_prepB<<<2000, 256>>>(gcn0_w, gcn_w);
    k_edge_embed<<<20000, 256>>>(edge_attr, edge_w, edge_b);

    const size_t LSZ = (size_t)2 * PAD * PAD;

    // layer 0: K=32 (1 chunk), no input relu
    k_gemm<0><<<1250, 256, SMW * 4>>>(bufA, bt, gcn0_b, bufB, 1);
    k_gather<<<12500, 256>>>(bufB);

    // layers 1..4: K=300 -> 10 chunks, relu on input
    for (int l = 1; l < 5; l++) {
        const float* in = (l & 1) ? bufB : bufA;
        float*       o  = (l & 1) ? bufA : bufB;
        k_gemm<1><<<1250, 256, SMW * 4>>>(in, bt + (size_t)l * LSZ,
                                          gcn_b + (size_t)(l - 1) * HID, o, 10);
        k_gather<<<12500, 256>>>(o);
    }

    k_mean<<<625, 320>>>(bufB);
    k_head<<<1, 320>>>(lin1_w, lin1_b, lin2_w, lin2_b, out);
}